// round 2
// baseline (speedup 1.0000x reference)
#include <cuda_runtime.h>

#define B_ 128
#define T_ 256
#define H_ 512
#define G_ 2048   // 4*H

// Static scratch (no allocations allowed)
__device__ float g_xproj[(size_t)2 * T_ * B_ * G_];   // [dir][t][b][4H] (per-layer, reused)
__device__ float g_hseq [(size_t)2 * T_ * B_ * H_];   // [dir][t][b][H]  layer-0 output
__device__ float g_h[2][2 * B_ * H_];                 // [parity][dir*B*H]
__device__ float g_c[2 * B_ * H_];                    // [dir*B*H]

__device__ __forceinline__ float2 ffma2(float2 a, float2 b, float2 c) {
    unsigned long long aa = *(unsigned long long*)&a;
    unsigned long long bb = *(unsigned long long*)&b;
    unsigned long long cc = *(unsigned long long*)&c;
    unsigned long long dd;
    asm("fma.rn.f32x2 %0, %1, %2, %3;" : "=l"(dd) : "l"(aa), "l"(bb), "l"(cc));
    return *(float2*)&dd;
}

__device__ __forceinline__ float sig_(float x) { return 1.0f / (1.0f + __expf(-x)); }

// ---------------------------------------------------------------------------
// Input projection: xproj[d][t][b][:] = inp . Wx[l,d] + bias[l,d]
// M=128 (batch rows at fixed t), N=2048, K=512. BM=BN=128, BK=16, 256 thr, 8x8.
// Grid: (T, 16, 2)
// ---------------------------------------------------------------------------
__global__ __launch_bounds__(256, 2)
void xproj_kernel(const float* __restrict__ x, const float* __restrict__ Wx,
                  const float* __restrict__ bias, int layer)
{
    __shared__ float sA[16][136];
    __shared__ float sB[16][136];

    const int tid = threadIdx.x;
    const int tx = tid & 15;       // 8 cols each
    const int ty = tid >> 4;       // 8 rows each
    const int t  = blockIdx.x;
    const int n0 = blockIdx.y << 7;
    const int d  = blockIdx.z;

    const float* Ab; size_t strA;
    if (layer == 0) {
        const int ts = d ? (T_ - 1 - t) : t;       // time reversal for bwd stack
        Ab = x + (size_t)ts * H_;                  // + b * (T*H)
        strA = (size_t)T_ * H_;
    } else {
        Ab = g_hseq + ((size_t)d * T_ + t) * B_ * H_;
        strA = H_;
    }
    const float* Bb = Wx + (size_t)(layer * 2 + d) * H_ * G_ + n0;

    float2 acc[8][4];
    #pragma unroll
    for (int i = 0; i < 8; i++)
        #pragma unroll
        for (int j = 0; j < 4; j++) acc[i][j] = make_float2(0.f, 0.f);

    for (int kb = 0; kb < H_; kb += 16) {
        #pragma unroll
        for (int rr = 0; rr < 2; rr++) {           // A: 128 rows x 16 k
            const int f4 = tid * 2 + rr;
            const int row = f4 >> 2;
            const int kq = (f4 & 3) * 4;
            const float4 v = *(const float4*)(Ab + (size_t)row * strA + kb + kq);
            sA[kq + 0][row] = v.x; sA[kq + 1][row] = v.y;
            sA[kq + 2][row] = v.z; sA[kq + 3][row] = v.w;
        }
        #pragma unroll
        for (int rr = 0; rr < 2; rr++) {           // B: 16 k x 128 cols
            const int f4 = tid * 2 + rr;
            const int kr = f4 >> 5;
            const int c4 = (f4 & 31) * 4;
            *(float4*)&sB[kr][c4] = *(const float4*)(Bb + (size_t)(kb + kr) * G_ + c4);
        }
        __syncthreads();
        #pragma unroll
        for (int k = 0; k < 16; k++) {
            const float4 a0 = *(const float4*)&sA[k][ty * 8];
            const float4 a1 = *(const float4*)&sA[k][ty * 8 + 4];
            const float4 b0 = *(const float4*)&sB[k][tx * 8];
            const float4 b1 = *(const float4*)&sB[k][tx * 8 + 4];
            const float av[8] = {a0.x, a0.y, a0.z, a0.w, a1.x, a1.y, a1.z, a1.w};
            const float2 bp[4] = {make_float2(b0.x, b0.y), make_float2(b0.z, b0.w),
                                  make_float2(b1.x, b1.y), make_float2(b1.z, b1.w)};
            #pragma unroll
            for (int i = 0; i < 8; i++) {
                const float2 ad = make_float2(av[i], av[i]);
                #pragma unroll
                for (int j = 0; j < 4; j++) acc[i][j] = ffma2(ad, bp[j], acc[i][j]);
            }
        }
        __syncthreads();
    }

    const float* bpt = bias + (size_t)(layer * 2 + d) * G_ + n0 + tx * 8;
    float bv[8];
    #pragma unroll
    for (int j = 0; j < 8; j++) bv[j] = bpt[j];

    float* ob = g_xproj + ((size_t)d * T_ + t) * B_ * G_ + n0 + tx * 8;
    #pragma unroll
    for (int i = 0; i < 8; i++) {
        const int b = ty * 8 + i;
        const float4 o0 = make_float4(acc[i][0].x + bv[0], acc[i][0].y + bv[1],
                                      acc[i][1].x + bv[2], acc[i][1].y + bv[3]);
        const float4 o1 = make_float4(acc[i][2].x + bv[4], acc[i][2].y + bv[5],
                                      acc[i][3].x + bv[6], acc[i][3].y + bv[7]);
        *(float4*)(ob + (size_t)b * G_)     = o0;
        *(float4*)(ob + (size_t)b * G_ + 4) = o1;
    }
}

// ---------------------------------------------------------------------------
// Fused recurrent step: gates = xproj[t] + h_prev @ Wh; apply LSTM cell.
// Grid: (16 hcol-tiles of 32, 4 row-tiles of 32, 2 dirs) = 128 CTAs, 128 thr.
// Thread owns 4 rows x 2 hcols x all 4 gates -> cell update is thread-local.
// h double-buffered by parity: read (t&1)^1, write t&1 (avoids cross-CTA race).
// ---------------------------------------------------------------------------
__global__ __launch_bounds__(128, 1)
void step_kernel(const float* __restrict__ Wh, float* __restrict__ out,
                 int layer, int t)
{
    __shared__ float sA[16][36];
    __shared__ float sB[16][132];

    const int tid = threadIdx.x;
    const int tx = tid & 15;       // 2 hcols each
    const int ty = tid >> 4;       // 4 rows each
    const int hc0 = blockIdx.x * 32;
    const int b0  = blockIdx.y * 32;
    const int d   = blockIdx.z;

    const float* Wb = Wh + (size_t)(layer * 2 + d) * H_ * G_;

    float2 acc[4][4];
    #pragma unroll
    for (int r = 0; r < 4; r++)
        #pragma unroll
        for (int g = 0; g < 4; g++) acc[r][g] = make_float2(0.f, 0.f);

    if (t > 0) {
        const float* hp = g_h[(t & 1) ^ 1] + d * B_ * H_ + (size_t)b0 * H_;
        for (int kb = 0; kb < H_; kb += 16) {
            {   // A: 32 rows x 16 k
                const int row = tid >> 2;
                const int kq = (tid & 3) * 4;
                const float4 v = *(const float4*)(hp + (size_t)row * H_ + kb + kq);
                sA[kq + 0][row] = v.x; sA[kq + 1][row] = v.y;
                sA[kq + 2][row] = v.z; sA[kq + 3][row] = v.w;
            }
            #pragma unroll
            for (int j = 0; j < 4; j++) {   // B: 16 k x (4 gates x 32 hc)
                const int idx = tid + j * 128;
                const int kr = idx >> 5;
                const int c4 = (idx & 31) * 4;
                const int gcol = (c4 >> 5) * H_ + hc0 + (c4 & 31);
                *(float4*)&sB[kr][c4] = *(const float4*)(Wb + (size_t)(kb + kr) * G_ + gcol);
            }
            __syncthreads();
            #pragma unroll
            for (int k = 0; k < 16; k++) {
                const float4 a = *(const float4*)&sA[k][ty * 4];
                const float av[4] = {a.x, a.y, a.z, a.w};
                float2 bg[4];
                #pragma unroll
                for (int g = 0; g < 4; g++)
                    bg[g] = *(const float2*)&sB[k][g * 32 + tx * 2];
                #pragma unroll
                for (int r = 0; r < 4; r++) {
                    const float2 ar = make_float2(av[r], av[r]);
                    #pragma unroll
                    for (int g = 0; g < 4; g++)
                        acc[r][g] = ffma2(ar, bg[g], acc[r][g]);
                }
            }
            __syncthreads();
        }
    }

    // Epilogue: add xproj, apply LSTM cell, write c/h/output
    const float* xp = g_xproj + ((size_t)d * T_ + t) * B_ * G_;
    float* hw = g_h[t & 1] + d * B_ * H_;
    float* cp = g_c + d * B_ * H_;
    const int hc = hc0 + tx * 2;

    #pragma unroll
    for (int r = 0; r < 4; r++) {
        const int b = b0 + ty * 4 + r;
        const float* xr = xp + (size_t)b * G_;
        float2 gi = acc[r][0], gf = acc[r][1], gg = acc[r][2], go = acc[r][3];
        const float2 xi = *(const float2*)(xr + hc);
        const float2 xf = *(const float2*)(xr + H_ + hc);
        const float2 xg = *(const float2*)(xr + 2 * H_ + hc);
        const float2 xo = *(const float2*)(xr + 3 * H_ + hc);
        gi.x += xi.x; gi.y += xi.y;  gf.x += xf.x; gf.y += xf.y;
        gg.x += xg.x; gg.y += xg.y;  go.x += xo.x; go.y += xo.y;

        float2 cold = (t > 0) ? *(const float2*)(cp + (size_t)b * H_ + hc)
                              : make_float2(0.f, 0.f);
        const float ix = sig_(gi.x), iy = sig_(gi.y);
        const float fx = sig_(gf.x), fy = sig_(gf.y);
        const float gx = tanhf(gg.x), gy = tanhf(gg.y);
        const float ox = sig_(go.x), oy = sig_(go.y);
        const float cnx = fx * cold.x + ix * gx;
        const float cny = fy * cold.y + iy * gy;
        const float hnx = ox * tanhf(cnx);
        const float hny = oy * tanhf(cny);

        *(float2*)(cp + (size_t)b * H_ + hc) = make_float2(cnx, cny);
        *(float2*)(hw + (size_t)b * H_ + hc) = make_float2(hnx, hny);

        if (layer == 0) {
            float* hs = g_hseq + ((size_t)d * T_ + t) * B_ * H_ + (size_t)b * H_ + hc;
            *(float2*)hs = make_float2(hnx, hny);
        } else {
            const int tr = d ? (T_ - 1 - t) : t;   // un-reverse bwd time
            float* op = out + ((size_t)b * T_ + tr) * (2 * H_) + d * H_ + hc;
            *(float2*)op = make_float2(hnx, hny);
        }
    }
}

extern "C" void kernel_launch(void* const* d_in, const int* in_sizes, int n_in,
                              void* d_out, int out_size)
{
    const float* x  = (const float*)d_in[0];
    const float* Wx = (const float*)d_in[1];
    const float* Wh = (const float*)d_in[2];
    const float* b  = (const float*)d_in[3];
    float* out = (float*)d_out;

    const dim3 gx(T_, 16, 2);   // xproj grid
    const dim3 gs(16, 4, 2);    // step grid (128 CTAs)

    for (int l = 0; l < 2; l++) {
        xproj_kernel<<<gx, 256>>>(x, Wx, b, l);
        for (int t = 0; t < T_; t++)
            step_kernel<<<gs, 128>>>(Wh, out, l, t);
    }
}

// round 3
// speedup vs baseline: 1.2673x; 1.2673x over previous
#include <cuda_runtime.h>

#define B_ 128
#define T_ 256
#define H_ 512
#define G_ 2048   // 4*H
#define NCTA 128u

// ---- static scratch (no allocations allowed) ----
__device__ float g_xproj[(size_t)2 * T_ * B_ * G_];   // [dir][t][b][4H]
__device__ float g_hseq [(size_t)2 * T_ * B_ * H_];   // [dir][t][b][H]  layer-0 output
__device__ float g_hT[2][2][H_][B_];                  // [parity][dir][hcol][b] (transposed h)
__device__ unsigned g_ctr;   // zero-init; reset at end of each persistent launch
__device__ unsigned g_rel;
__device__ unsigned g_done;

__device__ __forceinline__ float2 ffma2(float2 a, float2 b, float2 c) {
    unsigned long long aa = *(unsigned long long*)&a;
    unsigned long long bb = *(unsigned long long*)&b;
    unsigned long long cc = *(unsigned long long*)&c;
    unsigned long long dd;
    asm("fma.rn.f32x2 %0, %1, %2, %3;" : "=l"(dd) : "l"(aa), "l"(bb), "l"(cc));
    return *(float2*)&dd;
}
__device__ __forceinline__ float sig_(float x) { return 1.0f / (1.0f + __expf(-x)); }

__device__ __forceinline__ void cp16(void* smem, const void* gmem) {
    unsigned s = (unsigned)__cvta_generic_to_shared(smem);
    asm volatile("cp.async.cg.shared.global [%0], [%1], 16;" :: "r"(s), "l"(gmem));
}
#define CP_COMMIT() asm volatile("cp.async.commit_group;")
#define CP_WAIT2()  asm volatile("cp.async.wait_group 2;")

// grid-wide barrier: all 128 CTAs co-resident (grid <= SM count, 1 CTA/SM)
__device__ __forceinline__ void gridbar(unsigned phase) {
    __syncthreads();
    if (threadIdx.x == 0) {
        __threadfence();
        unsigned v = atomicAdd(&g_ctr, 1u) + 1u;
        if (v == phase * NCTA) {
            atomicExch(&g_rel, phase);
        } else {
            unsigned r;
            do {
                asm volatile("ld.global.acquire.gpu.u32 %0, [%1];" : "=r"(r) : "l"(&g_rel));
                if (r >= phase) break;
                __nanosleep(32);
            } while (true);
        }
        __threadfence();
    }
    __syncthreads();
}

// ---------------------------------------------------------------------------
// Input projection GEMM (unchanged from R2, known good): grid (T, 16, 2), 256 thr
// ---------------------------------------------------------------------------
__global__ __launch_bounds__(256, 2)
void xproj_kernel(const float* __restrict__ x, const float* __restrict__ Wx,
                  const float* __restrict__ bias, int layer)
{
    __shared__ float sA[16][136];
    __shared__ float sB[16][136];

    const int tid = threadIdx.x;
    const int tx = tid & 15, ty = tid >> 4;
    const int t  = blockIdx.x;
    const int n0 = blockIdx.y << 7;
    const int d  = blockIdx.z;

    const float* Ab; size_t strA;
    if (layer == 0) {
        const int ts = d ? (T_ - 1 - t) : t;
        Ab = x + (size_t)ts * H_;
        strA = (size_t)T_ * H_;
    } else {
        Ab = g_hseq + ((size_t)d * T_ + t) * B_ * H_;
        strA = H_;
    }
    const float* Bb = Wx + (size_t)(layer * 2 + d) * H_ * G_ + n0;

    float2 acc[8][4];
    #pragma unroll
    for (int i = 0; i < 8; i++)
        #pragma unroll
        for (int j = 0; j < 4; j++) acc[i][j] = make_float2(0.f, 0.f);

    for (int kb = 0; kb < H_; kb += 16) {
        #pragma unroll
        for (int rr = 0; rr < 2; rr++) {
            const int f4 = tid * 2 + rr;
            const int row = f4 >> 2;
            const int kq = (f4 & 3) * 4;
            const float4 v = *(const float4*)(Ab + (size_t)row * strA + kb + kq);
            sA[kq + 0][row] = v.x; sA[kq + 1][row] = v.y;
            sA[kq + 2][row] = v.z; sA[kq + 3][row] = v.w;
        }
        #pragma unroll
        for (int rr = 0; rr < 2; rr++) {
            const int f4 = tid * 2 + rr;
            const int kr = f4 >> 5;
            const int c4 = (f4 & 31) * 4;
            *(float4*)&sB[kr][c4] = *(const float4*)(Bb + (size_t)(kb + kr) * G_ + c4);
        }
        __syncthreads();
        #pragma unroll
        for (int k = 0; k < 16; k++) {
            const float4 a0 = *(const float4*)&sA[k][ty * 8];
            const float4 a1 = *(const float4*)&sA[k][ty * 8 + 4];
            const float4 b0 = *(const float4*)&sB[k][tx * 8];
            const float4 b1 = *(const float4*)&sB[k][tx * 8 + 4];
            const float av[8] = {a0.x, a0.y, a0.z, a0.w, a1.x, a1.y, a1.z, a1.w};
            const float2 bp[4] = {make_float2(b0.x, b0.y), make_float2(b0.z, b0.w),
                                  make_float2(b1.x, b1.y), make_float2(b1.z, b1.w)};
            #pragma unroll
            for (int i = 0; i < 8; i++) {
                const float2 ad = make_float2(av[i], av[i]);
                #pragma unroll
                for (int j = 0; j < 4; j++) acc[i][j] = ffma2(ad, bp[j], acc[i][j]);
            }
        }
        __syncthreads();
    }

    const float* bpt = bias + (size_t)(layer * 2 + d) * G_ + n0 + tx * 8;
    float bv[8];
    #pragma unroll
    for (int j = 0; j < 8; j++) bv[j] = bpt[j];

    float* ob = g_xproj + ((size_t)d * T_ + t) * B_ * G_ + n0 + tx * 8;
    #pragma unroll
    for (int i = 0; i < 8; i++) {
        const int b = ty * 8 + i;
        const float4 o0 = make_float4(acc[i][0].x + bv[0], acc[i][0].y + bv[1],
                                      acc[i][1].x + bv[2], acc[i][1].y + bv[3]);
        const float4 o1 = make_float4(acc[i][2].x + bv[4], acc[i][2].y + bv[5],
                                      acc[i][3].x + bv[6], acc[i][3].y + bv[7]);
        *(float4*)(ob + (size_t)b * G_)     = o0;
        *(float4*)(ob + (size_t)b * G_ + 4) = o1;
    }
}

// ---------------------------------------------------------------------------
// Persistent recurrence: one launch runs all 256 timesteps of one layer.
// 128 CTAs (16 hc-tiles x 4 row-tiles x 2 dirs), 128 threads.
// Thread owns 4 rows x 2 hcols x 4 gates; c-state lives in registers.
// Wh + h streamed via 4-stage cp.async.cg pipeline (L1-bypassing).
// ---------------------------------------------------------------------------
__global__ __launch_bounds__(128, 1)
void lstm_persist(const float* __restrict__ Wh, float* __restrict__ out, int layer)
{
    __shared__ float sW[4][16][128];   // 32 KB
    __shared__ float sA[4][16][32];    //  8 KB

    const int tid = threadIdx.x;
    const int tx = tid & 15;           // hc pair
    const int ty = tid >> 4;           // 4-row group (0..7)
    const int bidx = blockIdx.x;
    const int d   = bidx >> 6;
    const int rt  = (bidx >> 4) & 3;
    const int hcT = bidx & 15;
    const int b0  = rt * 32;
    const int hc0 = hcT * 32;
    const int hc  = hc0 + tx * 2;
    const int r0  = b0 + ty * 4;

    const float* Wb = Wh + (size_t)(layer * 2 + d) * H_ * G_;

    // precompute per-thread cp.async coordinates
    int wk[4], wc[4];                  // Wh chunks: k row, smem col (floats)
    const float* wsrc[4];
    #pragma unroll
    for (int j = 0; j < 4; j++) {
        const int idx = j * 128 + tid;
        const int k = idx >> 5, c16 = idx & 31;
        const int gate = c16 >> 3, part = c16 & 7;
        wk[j] = k; wc[j] = c16 * 4;
        wsrc[j] = Wb + (size_t)k * G_ + gate * H_ + hc0 + part * 4;
    }
    const int ak = tid >> 3, ac = (tid & 7) * 4;   // h chunk coords

    float2 cst[4];
    #pragma unroll
    for (int r = 0; r < 4; r++) cst[r] = make_float2(0.f, 0.f);

    for (int t = 0; t < T_; t++) {
        const int p = t & 1;

        // prefetch xproj slice into registers (hidden under GEMM)
        const float* xb = g_xproj + ((size_t)d * T_ + t) * B_ * G_;
        float2 xp[4][4];
        #pragma unroll
        for (int r = 0; r < 4; r++)
            #pragma unroll
            for (int g = 0; g < 4; g++)
                xp[r][g] = *(const float2*)(xb + (size_t)(r0 + r) * G_ + g * H_ + hc);

        float2 acc[4][4];
        #pragma unroll
        for (int r = 0; r < 4; r++)
            #pragma unroll
            for (int g = 0; g < 4; g++) acc[r][g] = make_float2(0.f, 0.f);

        if (t > 0) {
            const float* hsrc = &g_hT[p ^ 1][d][0][0];

            #define ISSUE(st, kb) do {                                         \
                _Pragma("unroll")                                              \
                for (int j = 0; j < 4; j++)                                    \
                    cp16(&sW[st][wk[j]][wc[j]], wsrc[j] + (size_t)(kb) * G_);  \
                cp16(&sA[st][ak][ac], hsrc + (size_t)((kb) + ak) * B_ + b0 + ac); \
                CP_COMMIT();                                                   \
            } while (0)

            ISSUE(0, 0); ISSUE(1, 16); ISSUE(2, 32);

            for (int kbi = 0; kbi < 32; kbi++) {
                CP_WAIT2();
                __syncthreads();
                const int s = kbi & 3;
                #pragma unroll
                for (int k = 0; k < 16; k++) {
                    const float4 av = *(const float4*)&sA[s][k][ty * 4];
                    float2 bg[4];
                    #pragma unroll
                    for (int g = 0; g < 4; g++)
                        bg[g] = *(const float2*)&sW[s][k][g * 32 + tx * 2];
                    const float ar[4] = {av.x, av.y, av.z, av.w};
                    #pragma unroll
                    for (int r = 0; r < 4; r++) {
                        const float2 a2 = make_float2(ar[r], ar[r]);
                        #pragma unroll
                        for (int g = 0; g < 4; g++)
                            acc[r][g] = ffma2(a2, bg[g], acc[r][g]);
                    }
                }
                const int nb = kbi + 3;
                if (nb < 32) ISSUE(nb & 3, nb * 16);
            }
            #undef ISSUE
        }

        // epilogue: gates -> cell -> h
        float2 hv[4];
        #pragma unroll
        for (int r = 0; r < 4; r++) {
            const float i0 = sig_(acc[r][0].x + xp[r][0].x);
            const float i1 = sig_(acc[r][0].y + xp[r][0].y);
            const float f0 = sig_(acc[r][1].x + xp[r][1].x);
            const float f1 = sig_(acc[r][1].y + xp[r][1].y);
            const float q0 = tanhf(acc[r][2].x + xp[r][2].x);
            const float q1 = tanhf(acc[r][2].y + xp[r][2].y);
            const float o0 = sig_(acc[r][3].x + xp[r][3].x);
            const float o1 = sig_(acc[r][3].y + xp[r][3].y);
            cst[r].x = f0 * cst[r].x + i0 * q0;
            cst[r].y = f1 * cst[r].y + i1 * q1;
            hv[r] = make_float2(o0 * tanhf(cst[r].x), o1 * tanhf(cst[r].y));
        }

        // write transposed h for next step: [hcol][b], 4 consecutive rows
        const float4 ha = make_float4(hv[0].x, hv[1].x, hv[2].x, hv[3].x);
        const float4 hb = make_float4(hv[0].y, hv[1].y, hv[2].y, hv[3].y);
        *(float4*)&g_hT[p][d][hc][r0]     = ha;
        *(float4*)&g_hT[p][d][hc + 1][r0] = hb;

        if (layer == 0) {
            float* hs = g_hseq + ((size_t)d * T_ + t) * B_ * H_;
            #pragma unroll
            for (int r = 0; r < 4; r++)
                *(float2*)(hs + (size_t)(r0 + r) * H_ + hc) = hv[r];
        } else {
            const int tr = d ? (T_ - 1 - t) : t;
            #pragma unroll
            for (int r = 0; r < 4; r++)
                *(float2*)(out + ((size_t)(r0 + r) * T_ + tr) * (2 * H_) + d * H_ + hc) = hv[r];
        }

        if (t < T_ - 1) gridbar((unsigned)(t + 1));
    }

    // self-reset barrier state for the next launch / graph replay
    __syncthreads();
    if (tid == 0) {
        __threadfence();
        const unsigned v = atomicAdd(&g_done, 1u);
        if (v == NCTA - 1u) {
            atomicExch(&g_ctr, 0u);
            atomicExch(&g_rel, 0u);
            atomicExch(&g_done, 0u);
        }
    }
}

extern "C" void kernel_launch(void* const* d_in, const int* in_sizes, int n_in,
                              void* d_out, int out_size)
{
    const float* x  = (const float*)d_in[0];
    const float* Wx = (const float*)d_in[1];
    const float* Wh = (const float*)d_in[2];
    const float* b  = (const float*)d_in[3];
    float* out = (float*)d_out;

    const dim3 gx(T_, 16, 2);
    for (int l = 0; l < 2; l++) {
        xproj_kernel<<<gx, 256>>>(x, Wx, b, l);
        lstm_persist<<<NCTA, 128>>>(Wh, out, l);
    }
}

// round 6
// speedup vs baseline: 1.7148x; 1.3531x over previous
#include <cuda_runtime.h>
#include <cstdint>

#define B_ 128
#define T_ 256
#define H_ 512
#define G_ 2048   // 4*H
#define NCTA 128u
#define PAD_ 36

// ---- static scratch ----
__device__ float g_xproj[(size_t)2 * T_ * B_ * G_];   // [dir][t][b][4H]
__device__ float g_hseq [(size_t)2 * T_ * B_ * H_];   // [dir][t][b][H] (tf32-rounded)
__device__ float g_hT[2][2][H_][B_];                  // [parity][dir][hcol][b]
__device__ float g_xR[(size_t)B_ * T_ * H_];          // tf32-rounded x
__device__ float g_Wfrag[(size_t)4 * G_ * H_];        // fragment-swizzled tf32 Wx
__device__ unsigned g_ctr;
__device__ unsigned g_rel;
__device__ unsigned g_done;

// ---------------- helpers ----------------
__device__ __forceinline__ float2 ffma2(float2 a, float2 b, float2 c) {
    unsigned long long aa = *(unsigned long long*)&a;
    unsigned long long bb = *(unsigned long long*)&b;
    unsigned long long cc = *(unsigned long long*)&c;
    unsigned long long dd;
    asm("fma.rn.f32x2 %0, %1, %2, %3;" : "=l"(dd) : "l"(aa), "l"(bb), "l"(cc));
    return *(float2*)&dd;
}
__device__ __forceinline__ float sig_(float x) { return 1.0f / (1.0f + __expf(-x)); }
__device__ __forceinline__ float rtf32(float v) {
    uint32_t u; asm("cvt.rna.tf32.f32 %0, %1;" : "=r"(u) : "f"(v));
    return __uint_as_float(u);
}
__device__ __forceinline__ void cp16(void* smem, const void* gmem) {
    unsigned s = (unsigned)__cvta_generic_to_shared(smem);
    asm volatile("cp.async.cg.shared.global [%0], [%1], 16;" :: "r"(s), "l"(gmem));
}
#define CP_COMMIT()  asm volatile("cp.async.commit_group;")
#define CP_WAIT1()   asm volatile("cp.async.wait_group 1;")
#define CP_WAIT2()   asm volatile("cp.async.wait_group 2;")
#define CP_WAITALL() asm volatile("cp.async.wait_group 0;")

__device__ __forceinline__ void mma8(float* c, const uint32_t* a, const uint32_t* b) {
    asm volatile(
        "mma.sync.aligned.m16n8k8.row.col.f32.tf32.tf32.f32 "
        "{%0,%1,%2,%3}, {%4,%5,%6,%7}, {%8,%9}, {%0,%1,%2,%3};"
        : "+f"(c[0]), "+f"(c[1]), "+f"(c[2]), "+f"(c[3])
        : "r"(a[0]), "r"(a[1]), "r"(a[2]), "r"(a[3]), "r"(b[0]), "r"(b[1]));
}

// grid-wide barrier for the persistent kernel (128 CTAs, 1/SM)
__device__ __forceinline__ void gridbar(unsigned phase) {
    __syncthreads();
    if (threadIdx.x == 0) {
        __threadfence();
        unsigned v = atomicAdd(&g_ctr, 1u) + 1u;
        if (v == phase * NCTA) {
            atomicExch(&g_rel, phase);
        } else {
            unsigned r;
            do {
                asm volatile("ld.global.acquire.gpu.u32 %0, [%1];" : "=r"(r) : "l"(&g_rel));
                if (r >= phase) break;
                __nanosleep(32);
            } while (true);
        }
        __threadfence();
    }
    __syncthreads();
}

// ---------------------------------------------------------------------------
// Prep 1: tf32-round x into g_xR
// ---------------------------------------------------------------------------
__global__ __launch_bounds__(256, 4)
void round_x(const float* __restrict__ x)
{
    const size_t i = ((size_t)blockIdx.x * 256 + threadIdx.x) * 4;
    const float4 v = *(const float4*)(x + i);
    float4 o;
    o.x = rtf32(v.x); o.y = rtf32(v.y); o.z = rtf32(v.z); o.w = rtf32(v.w);
    *(float4*)(g_xR + i) = o;
}

// ---------------------------------------------------------------------------
// Prep 2: build fragment-swizzled tf32 Wx.
// chunk id cid = ((p*2048 + n)*16 + kb)*4 + r  (p=l*2+d, n col, kb k-block, r=lane%4)
// chunk[ks*2 + b01] = tf32( Wx[p][kb*32 + ks*8 + r + 4*b01][n] )
// ---------------------------------------------------------------------------
__global__ __launch_bounds__(256, 4)
void prep_wfrag(const float* __restrict__ Wx)
{
    const uint32_t cid = blockIdx.x * 256 + threadIdx.x;   // 524288 total
    const int r  = cid & 3;
    const int kb = (cid >> 2) & 15;
    const int n  = (cid >> 6) & 2047;
    const int p  = cid >> 17;
    const float* W = Wx + (size_t)p * H_ * G_;
    float* o = g_Wfrag + (size_t)cid * 8;
    #pragma unroll
    for (int ks = 0; ks < 4; ks++)
        #pragma unroll
        for (int b01 = 0; b01 < 2; b01++) {
            const int k = kb * 32 + ks * 8 + r + 4 * b01;
            o[ks * 2 + b01] = rtf32(W[(size_t)k * G_ + n]);
        }
}

// ---------------------------------------------------------------------------
// tf32 mma.sync xproj GEMM: per CTA D[128 x 128], K=512 in 16 k-blocks of 32.
// 256 thr = 8 warps (2 m x 4 n); warp = 4x4 m16n8k8 tiles.
// A via 3-stage cp.async SMEM pipeline; B direct LDG from g_Wfrag.
// Grid (T, 16, 2). Dynamic smem = 3*128*36*4 = 55296 B.
// ---------------------------------------------------------------------------
#define XP_SMEM (3 * 128 * PAD_ * 4)

__global__ __launch_bounds__(256, 1)
void xproj_mma(const float* __restrict__ bias, int layer)
{
    extern __shared__ float sA[];   // [3][128][PAD_]

    const int tid = threadIdx.x;
    const int lane = tid & 31, wid = tid >> 5;
    const int wm = wid & 1, wn = wid >> 1;
    const int tg = lane >> 2, r4 = lane & 3;
    const int t = blockIdx.x, d = blockIdx.z;
    const int n0 = blockIdx.y * 128;
    const int l2d = layer * 2 + d;

    const float* Ab; size_t strA;
    if (layer == 0) {
        const int ts = d ? (T_ - 1 - t) : t;
        Ab = g_xR + (size_t)ts * H_;
        strA = (size_t)T_ * H_;
    } else {
        Ab = g_hseq + ((size_t)d * T_ + t) * B_ * H_;
        strA = H_;
    }

    // B fragment base pointers (per ntile)
    const float* pB[4];
    #pragma unroll
    for (int nt = 0; nt < 4; nt++) {
        const int n = n0 + wn * 32 + nt * 8 + tg;
        pB[nt] = g_Wfrag + ((size_t)((l2d * 2048 + n) * 64 + r4)) * 8;
    }

    // per-thread cp.async coords: 4 chunks of 16B
    const int crow[4] = {tid >> 3, (256 + tid) >> 3, (512 + tid) >> 3, (768 + tid) >> 3};
    const int cc4 = tid & 7;

    #define ISSUE(st, kb) do {                                               \
        _Pragma("unroll")                                                    \
        for (int i = 0; i < 4; i++)                                          \
            cp16(&sA[(st) * (128 * PAD_) + crow[i] * PAD_ + cc4 * 4],        \
                 Ab + (size_t)crow[i] * strA + (kb) * 32 + cc4 * 4);         \
        CP_COMMIT();                                                         \
    } while (0)

    float acc[4][4][4];
    #pragma unroll
    for (int mt = 0; mt < 4; mt++)
        #pragma unroll
        for (int nt = 0; nt < 4; nt++)
            #pragma unroll
            for (int i = 0; i < 4; i++) acc[mt][nt][i] = 0.f;

    ISSUE(0, 0);
    ISSUE(1, 1);

    for (int kb = 0; kb < 16; kb++) {
        // B fragments for this k-block (direct from L2)
        float4 bt[4][2];
        #pragma unroll
        for (int nt = 0; nt < 4; nt++) {
            bt[nt][0] = *(const float4*)(pB[nt] + kb * 32);
            bt[nt][1] = *(const float4*)(pB[nt] + kb * 32 + 4);
        }

        if (kb == 15) { CP_WAITALL(); } else { CP_WAIT1(); }
        __syncthreads();
        if (kb + 2 < 16) ISSUE((kb + 2) % 3, kb + 2);

        const float* sAs = sA + (kb % 3) * (128 * PAD_);
        #pragma unroll
        for (int ks = 0; ks < 4; ks++) {
            uint32_t a[4][4];
            #pragma unroll
            for (int mt = 0; mt < 4; mt++) {
                const int m = wm * 64 + mt * 16 + tg;
                const int k = ks * 8 + r4;
                a[mt][0] = __float_as_uint(sAs[m * PAD_ + k]);
                a[mt][1] = __float_as_uint(sAs[(m + 8) * PAD_ + k]);
                a[mt][2] = __float_as_uint(sAs[m * PAD_ + k + 4]);
                a[mt][3] = __float_as_uint(sAs[(m + 8) * PAD_ + k + 4]);
            }
            #pragma unroll
            for (int mt = 0; mt < 4; mt++)
                #pragma unroll
                for (int nt = 0; nt < 4; nt++) {
                    const float* bf = (ks < 2) ? (const float*)&bt[nt][0]
                                               : (const float*)&bt[nt][1];
                    uint32_t b2[2];
                    b2[0] = __float_as_uint(bf[(ks & 1) * 2]);
                    b2[1] = __float_as_uint(bf[(ks & 1) * 2 + 1]);
                    mma8(acc[mt][nt], a[mt], b2);
                }
        }
    }
    #undef ISSUE

    // epilogue: bias + store to g_xproj[d][t][b][n]
    float* ob = g_xproj + ((size_t)d * T_ + t) * B_ * G_;
    const float* bp = bias + (size_t)l2d * G_;
    #pragma unroll
    for (int nt = 0; nt < 4; nt++) {
        const int n = n0 + wn * 32 + nt * 8 + 2 * r4;
        const float2 bv = *(const float2*)(bp + n);
        #pragma unroll
        for (int mt = 0; mt < 4; mt++) {
            const int m = wm * 64 + mt * 16 + tg;
            float2 lo = make_float2(acc[mt][nt][0] + bv.x, acc[mt][nt][1] + bv.y);
            float2 hi = make_float2(acc[mt][nt][2] + bv.x, acc[mt][nt][3] + bv.y);
            *(float2*)(ob + (size_t)m * G_ + n)       = lo;
            *(float2*)(ob + (size_t)(m + 8) * G_ + n) = hi;
        }
    }
}

// ---------------------------------------------------------------------------
// Persistent fp32 recurrence (R3-proven; only change: tf32-round hseq stores)
// ---------------------------------------------------------------------------
__global__ __launch_bounds__(128, 1)
void lstm_persist(const float* __restrict__ Wh, float* __restrict__ out, int layer)
{
    __shared__ float sW[4][16][128];
    __shared__ float sA[4][16][32];

    const int tid = threadIdx.x;
    const int tx = tid & 15;
    const int ty = tid >> 4;
    const int bidx = blockIdx.x;
    const int d   = bidx >> 6;
    const int rt  = (bidx >> 4) & 3;
    const int hcT = bidx & 15;
    const int b0  = rt * 32;
    const int hc0 = hcT * 32;
    const int hc  = hc0 + tx * 2;
    const int r0  = b0 + ty * 4;

    const float* Wb = Wh + (size_t)(layer * 2 + d) * H_ * G_;

    int wk[4], wc[4];
    const float* wsrc[4];
    #pragma unroll
    for (int j = 0; j < 4; j++) {
        const int idx = j * 128 + tid;
        const int k = idx >> 5, c16 = idx & 31;
        const int gate = c16 >> 3, part = c16 & 7;
        wk[j] = k; wc[j] = c16 * 4;
        wsrc[j] = Wb + (size_t)k * G_ + gate * H_ + hc0 + part * 4;
    }
    const int ak = tid >> 3, ac = (tid & 7) * 4;

    float2 cst[4];
    #pragma unroll
    for (int r = 0; r < 4; r++) cst[r] = make_float2(0.f, 0.f);

    for (int t = 0; t < T_; t++) {
        const int p = t & 1;
        const float* xb = g_xproj + ((size_t)d * T_ + t) * B_ * G_;
        float2 xp[4][4];
        #pragma unroll
        for (int r = 0; r < 4; r++)
            #pragma unroll
            for (int g = 0; g < 4; g++)
                xp[r][g] = *(const float2*)(xb + (size_t)(r0 + r) * G_ + g * H_ + hc);

        float2 acc[4][4];
        #pragma unroll
        for (int r = 0; r < 4; r++)
            #pragma unroll
            for (int g = 0; g < 4; g++) acc[r][g] = make_float2(0.f, 0.f);

        if (t > 0) {
            const float* hsrc = &g_hT[p ^ 1][d][0][0];
            #define ISSUE2(st, kb) do {                                          \
                _Pragma("unroll")                                                \
                for (int j = 0; j < 4; j++)                                      \
                    cp16(&sW[st][wk[j]][wc[j]], wsrc[j] + (size_t)(kb) * G_);    \
                cp16(&sA[st][ak][ac], hsrc + (size_t)((kb) + ak) * B_ + b0 + ac);\
                CP_COMMIT();                                                     \
            } while (0)

            ISSUE2(0, 0); ISSUE2(1, 16); ISSUE2(2, 32);

            for (int kbi = 0; kbi < 32; kbi++) {
                CP_WAIT2();
                __syncthreads();
                const int s = kbi & 3;
                #pragma unroll
                for (int k = 0; k < 16; k++) {
                    const float4 av = *(const float4*)&sA[s][k][ty * 4];
                    float2 bg[4];
                    #pragma unroll
                    for (int g = 0; g < 4; g++)
                        bg[g] = *(const float2*)&sW[s][k][g * 32 + tx * 2];
                    const float ar[4] = {av.x, av.y, av.z, av.w};
                    #pragma unroll
                    for (int r = 0; r < 4; r++) {
                        const float2 a2 = make_float2(ar[r], ar[r]);
                        #pragma unroll
                        for (int g = 0; g < 4; g++)
                            acc[r][g] = ffma2(a2, bg[g], acc[r][g]);
                    }
                }
                const int nb = kbi + 3;
                if (nb < 32) ISSUE2(nb & 3, nb * 16);
            }
            #undef ISSUE2
        }

        float2 hv[4];
        #pragma unroll
        for (int r = 0; r < 4; r++) {
            const float i0 = sig_(acc[r][0].x + xp[r][0].x);
            const float i1 = sig_(acc[r][0].y + xp[r][0].y);
            const float f0 = sig_(acc[r][1].x + xp[r][1].x);
            const float f1 = sig_(acc[r][1].y + xp[r][1].y);
            const float q0 = tanhf(acc[r][2].x + xp[r][2].x);
            const float q1 = tanhf(acc[r][2].y + xp[r][2].y);
            const float o0 = sig_(acc[r][3].x + xp[r][3].x);
            const float o1 = sig_(acc[r][3].y + xp[r][3].y);
            cst[r].x = f0 * cst[r].x + i0 * q0;
            cst[r].y = f1 * cst[r].y + i1 * q1;
            hv[r] = make_float2(o0 * tanhf(cst[r].x), o1 * tanhf(cst[r].y));
        }

        const float4 ha = make_float4(hv[0].x, hv[1].x, hv[2].x, hv[3].x);
        const float4 hb = make_float4(hv[0].y, hv[1].y, hv[2].y, hv[3].y);
        *(float4*)&g_hT[p][d][hc][r0]     = ha;
        *(float4*)&g_hT[p][d][hc + 1][r0] = hb;

        if (layer == 0) {
            float* hs = g_hseq + ((size_t)d * T_ + t) * B_ * H_;
            #pragma unroll
            for (int r = 0; r < 4; r++) {
                float2 hr = make_float2(rtf32(hv[r].x), rtf32(hv[r].y));
                *(float2*)(hs + (size_t)(r0 + r) * H_ + hc) = hr;
            }
        } else {
            const int tr = d ? (T_ - 1 - t) : t;
            #pragma unroll
            for (int r = 0; r < 4; r++)
                *(float2*)(out + ((size_t)(r0 + r) * T_ + tr) * (2 * H_) + d * H_ + hc) = hv[r];
        }

        if (t < T_ - 1) gridbar((unsigned)(t + 1));
    }

    __syncthreads();
    if (tid == 0) {
        __threadfence();
        const unsigned v = atomicAdd(&g_done, 1u);
        if (v == NCTA - 1u) {
            atomicExch(&g_ctr, 0u);
            atomicExch(&g_rel, 0u);
            atomicExch(&g_done, 0u);
        }
    }
}

extern "C" void kernel_launch(void* const* d_in, const int* in_sizes, int n_in,
                              void* d_out, int out_size)
{
    const float* x  = (const float*)d_in[0];
    const float* Wx = (const float*)d_in[1];
    const float* Wh = (const float*)d_in[2];
    const float* b  = (const float*)d_in[3];
    float* out = (float*)d_out;

    static bool attr_done = false;
    if (!attr_done) {
        cudaFuncSetAttribute(xproj_mma, cudaFuncAttributeMaxDynamicSharedMemorySize, XP_SMEM);
        attr_done = true;
    }

    round_x<<<(B_ * T_ * H_ / 4 + 255) / 256, 256>>>(x);
    prep_wfrag<<<2048, 256>>>(Wx);
    for (int l = 0; l < 2; l++) {
        xproj_mma<<<dim3(T_, 16, 2), 256, XP_SMEM>>>(b, l);
        lstm_persist<<<NCTA, 128>>>(Wh, out, l);
    }
}